// round 2
// baseline (speedup 1.0000x reference)
#include <cuda_runtime.h>
#include <math.h>

#define BB   16
#define CINN 64
#define COUTT 64
#define HH   256
#define WW   256
#define M1N  32
#define M2N  32
#define KXN  64   // 2*M1 (rows 0..31 and 224..255)

// Scratch: spectral intermediates, ~16.8MB each.
__device__ float2 g_Xf  [BB * CINN  * KXN * M2N];  // [b][i][kxi][ky]
__device__ float2 g_T   [BB * COUTT * KXN * M2N];  // [b][c][kxi][ky]
__device__ float2 g_OutF[BB * COUTT * KXN * M2N];  // [b][o][kxi][ky]

// ---------------------------------------------------------------------------
// K12: partial rfft2 to the 64x32 mode corner.
// Xf[b,i,kxi,ky] = (1/256) * sum_h e^{-2pi i kx h/256} * sum_w x[h,w] e^{-2pi i ky w/256}
// kx = kxi (<32) or 192+kxi (kxi>=32  -> rows 224..255).
// W-axis uses real-input even/odd folding (127 paired terms).
// ---------------------------------------------------------------------------
__global__ void __launch_bounds__(256) k12_forward(const float* __restrict__ x) {
    __shared__ float  sx[8][256];
    __shared__ float2 eo[8][128];    // (even,odd) pairs, w=1..127
    __shared__ float2 sxw[8][32];    // per-row W-DFT result
    __shared__ float2 tw[256];       // e^{-2pi i k/256}

    const int tid = threadIdx.x;
    const int i = blockIdx.x, b = blockIdx.y;
    {
        float s, c;
        sincospif((float)tid / 128.0f, &s, &c);
        tw[tid] = make_float2(c, -s);
    }
    const int ky  = tid & 31;         // stage-2 ownership
    const int kx0 = (tid >> 5) << 3;  // 8 kxi per thread
    float2 acc[8];
#pragma unroll
    for (int j = 0; j < 8; j++) acc[j] = make_float2(0.f, 0.f);

    const float* xrow = x + (size_t)(b * CINN + i) * HH * WW;
    const int hl_s1 = tid >> 5;
    const int ky_s1 = tid & 31;

    for (int hb = 0; hb < HH; hb += 8) {
        __syncthreads();   // prev stage-2 done reading sxw / prev prep done
#pragma unroll
        for (int r = 0; r < 8; r++)
            sx[r][tid] = xrow[(hb + r) * WW + tid];
        __syncthreads();
        // even/odd prep
        {
            int hl = tid >> 5;
            for (int w = (tid & 31) + 1; w < 128; w += 32) {
                float a = sx[hl][w], bb2 = sx[hl][256 - w];
                eo[hl][w] = make_float2(a + bb2, a - bb2);
            }
        }
        __syncthreads();
        // stage 1: W-axis partial DFT (per (h-local, ky))
        {
            float x0 = sx[hl_s1][0], x128 = sx[hl_s1][128];
            float re = x0 + ((ky_s1 & 1) ? -x128 : x128);
            float im = 0.f;
            int idx = ky_s1;
#pragma unroll 127
            for (int w = 1; w < 128; w++) {
                float2 e = eo[hl_s1][w];
                float2 t = tw[idx];
                re = fmaf(e.x, t.x, re);
                im = fmaf(e.y, t.y, im);      // t.y = -sin
                idx = (idx + ky_s1) & 255;
            }
            sxw[hl_s1][ky_s1] = make_float2(re, im);
        }
        __syncthreads();
        // stage 2: H-axis partial DFT accumulate into registers
#pragma unroll
        for (int hl = 0; hl < 8; hl++) {
            float2 xv = sxw[hl][ky];
            int h = hb + hl;
#pragma unroll
            for (int j = 0; j < 8; j++) {
                int kxi = kx0 + j;
                int kx = (kxi < 32) ? kxi : (192 + kxi);
                float2 t = tw[(kx * h) & 255];
                acc[j].x = fmaf(xv.x, t.x, fmaf(-xv.y, t.y, acc[j].x));
                acc[j].y = fmaf(xv.x, t.y, fmaf( xv.y, t.x, acc[j].y));
            }
        }
    }
    const float sc = 1.0f / 256.0f;   // ortho forward scaling
#pragma unroll
    for (int j = 0; j < 8; j++) {
        g_Xf[((b * CINN + i) * KXN + kx0 + j) * M2N + ky] =
            make_float2(acc[j].x * sc, acc[j].y * sc);
    }
}

// ---------------------------------------------------------------------------
// K3a: t[b,c,kxi,ky] = sum_i Xf[b,i,kxi,ky] * w{1|2}[i,c,m],  m = kxi or kxi-32
// ---------------------------------------------------------------------------
__global__ void __launch_bounds__(256) k3a_mixx(const float* __restrict__ wx1,
                                                const float* __restrict__ wx2) {
    __shared__ float2 sX[CINN][M2N];    // 16KB
    __shared__ float2 sW[CINN][COUTT];  // 32KB
    const int tid = threadIdx.x;
    const int kxi = blockIdx.x, b = blockIdx.y;
    const int m = (kxi < 32) ? kxi : (kxi - 32);
    const float2* wsrc = (const float2*)((kxi < 32) ? wx1 : wx2);

    for (int idx = tid; idx < CINN * M2N; idx += 256) {
        int i = idx >> 5, k = idx & 31;
        sX[i][k] = g_Xf[((b * CINN + i) * KXN + kxi) * M2N + k];
    }
    for (int idx = tid; idx < CINN * COUTT; idx += 256) {
        int i = idx >> 6, c = idx & 63;
        sW[i][c] = wsrc[(i * COUTT + c) * M1N + m];
    }
    __syncthreads();

    const int ky = tid & 31;
    const int cb = (tid >> 5) << 3;
    float2 acc[8];
#pragma unroll
    for (int j = 0; j < 8; j++) acc[j] = make_float2(0.f, 0.f);
    for (int i = 0; i < CINN; i++) {
        float2 xv = sX[i][ky];
#pragma unroll
        for (int j = 0; j < 8; j++) {
            float2 wv = sW[i][cb + j];
            acc[j].x = fmaf(xv.x, wv.x, fmaf(-xv.y, wv.y, acc[j].x));
            acc[j].y = fmaf(xv.x, wv.y, fmaf( xv.y, wv.x, acc[j].y));
        }
    }
#pragma unroll
    for (int j = 0; j < 8; j++)
        g_T[((b * COUTT + cb + j) * KXN + kxi) * M2N + ky] = acc[j];
}

// ---------------------------------------------------------------------------
// K3b: OutF[b,o,kxi,ky] = sum_c t[b,c,kxi,ky] * wy[c,o,ky]
// ---------------------------------------------------------------------------
__global__ void __launch_bounds__(256) k3b_mixy(const float* __restrict__ wy) {
    __shared__ float2 sT[32][KXN];     // 16KB (c-chunk x kxi)
    __shared__ float2 sWy[32][COUTT];  // 16KB
    const int tid = threadIdx.x;
    const int ky = blockIdx.x, b = blockIdx.y;
    const int kxi = tid & 63;
    const int ob = (tid >> 6) << 4;
    const float2* wyp = (const float2*)wy;

    float2 acc[16];
#pragma unroll
    for (int j = 0; j < 16; j++) acc[j] = make_float2(0.f, 0.f);

    for (int cb = 0; cb < COUTT; cb += 32) {
        __syncthreads();
        for (int idx = tid; idx < 32 * KXN; idx += 256) {
            int cl = idx >> 6, kk = idx & 63;
            sT[cl][kk] = g_T[((b * COUTT + cb + cl) * KXN + kk) * M2N + ky];
        }
        for (int idx = tid; idx < 32 * COUTT; idx += 256) {
            int cl = idx >> 6, o = idx & 63;
            sWy[cl][o] = wyp[((cb + cl) * COUTT + o) * M2N + ky];
        }
        __syncthreads();
        for (int cl = 0; cl < 32; cl++) {
            float2 tv = sT[cl][kxi];
#pragma unroll
            for (int j = 0; j < 16; j++) {
                float2 wv = sWy[cl][ob + j];
                acc[j].x = fmaf(tv.x, wv.x, fmaf(-tv.y, wv.y, acc[j].x));
                acc[j].y = fmaf(tv.x, wv.y, fmaf( tv.y, wv.x, acc[j].y));
            }
        }
    }
#pragma unroll
    for (int j = 0; j < 16; j++)
        g_OutF[((b * COUTT + ob + j) * KXN + kxi) * M2N + ky] = acc[j];
}

// ---------------------------------------------------------------------------
// K45: fused inverse. Per (b,o,16-row h tile):
//   phase A: Z[h,ky] = sum_kxi OutF[kxi,ky] e^{+2pi i kx h/256}
//   phase B: out[h,w] = (1/256)*( Re Z[h,0] + 2*sum_{ky=1..31} Re(Z[h,ky] e^{+2pi i ky w/256}) )
//   with w <-> 256-w pairing (shared cos, sign-flipped sin).
// ---------------------------------------------------------------------------
__global__ void __launch_bounds__(256) k45_inverse(float* __restrict__ out) {
    __shared__ float2 sF[KXN][M2N];  // 16KB
    __shared__ float2 tw[256];       // e^{+2pi i k/256}
    __shared__ float2 sZ[16][M2N];   // 4KB

    const int tid = threadIdx.x;
    const int hb = blockIdx.x;       // 0..15 (tiles of 16 rows)
    const int o = blockIdx.y, b = blockIdx.z;
    {
        float s, c;
        sincospif((float)tid / 128.0f, &s, &c);
        tw[tid] = make_float2(c, s);
    }
    const float2* src = g_OutF + (size_t)(b * COUTT + o) * KXN * M2N;
    for (int idx = tid; idx < KXN * M2N; idx += 256)
        sF[idx >> 5][idx & 31] = src[idx];
    __syncthreads();

    // phase A
    const int hl = tid >> 4;
    const int kyp = tid & 15;
    const int h = hb * 16 + hl;
#pragma unroll
    for (int s = 0; s < 2; s++) {
        int kyA = kyp + s * 16;
        float re = 0.f, im = 0.f;
#pragma unroll 8
        for (int kxi = 0; kxi < KXN; kxi++) {
            int kx = (kxi < 32) ? kxi : (192 + kxi);
            float2 v = sF[kxi][kyA];
            float2 t = tw[(kx * h) & 255];
            re = fmaf(v.x, t.x, fmaf(-v.y, t.y, re));
            im = fmaf(v.x, t.y, fmaf( v.y, t.x, im));
        }
        sZ[hl][kyA] = make_float2(re, im);
    }
    __syncthreads();

    // phase B
    const int p  = tid & 127;
    const int hh = tid >> 7;
    const float sc = 1.0f / 256.0f;  // ortho inverse scaling
    float* orow = out + ((size_t)(b * COUTT + o) * HH + hb * 16) * WW;
    for (int hl2 = hh * 8; hl2 < hh * 8 + 8; hl2++) {
        float zr0 = sZ[hl2][0].x;
        float accA = 0.f, accB = 0.f;
        int idx = p;
#pragma unroll 31
        for (int ky = 1; ky < 32; ky++) {
            float2 z = sZ[hl2][ky];
            float2 t = tw[idx];
            accA = fmaf(z.x, t.x, accA);   // Re*cos
            accB = fmaf(z.y, t.y, accB);   // Im*sin
            idx = (idx + p) & 255;
        }
        orow[hl2 * WW + p] = (zr0 + 2.f * (accA - accB)) * sc;
        if (p > 0) {
            orow[hl2 * WW + (256 - p)] = (zr0 + 2.f * (accA + accB)) * sc;
        } else {
            // w = 128 (Nyquist column of the pairing): cos = (-1)^ky, sin = 0
            float a128 = 0.f;
#pragma unroll 31
            for (int ky = 1; ky < 32; ky++) {
                float zr = sZ[hl2][ky].x;
                a128 += (ky & 1) ? -zr : zr;
            }
            orow[hl2 * WW + 128] = (zr0 + 2.f * a128) * sc;
        }
    }
}

extern "C" void kernel_launch(void* const* d_in, const int* in_sizes, int n_in,
                              void* d_out, int out_size) {
    const float* x   = (const float*)d_in[0];
    const float* wx1 = (const float*)d_in[1];
    const float* wx2 = (const float*)d_in[2];
    const float* wy  = (const float*)d_in[3];
    float* out = (float*)d_out;

    k12_forward<<<dim3(CINN, BB), 256>>>(x);
    k3a_mixx  <<<dim3(KXN, BB), 256>>>(wx1, wx2);
    k3b_mixy  <<<dim3(M2N, BB), 256>>>(wy);
    k45_inverse<<<dim3(16, COUTT, BB), 256>>>(out);
}